// round 1
// baseline (speedup 1.0000x reference)
#include <cuda_runtime.h>

// Neo-Hookean 3D material point: psi, Cauchy (Voigt 6), DDSDDE (6x6) per point.
// Output layout (flattened tuple): [N] psi | [N,6] Cauchy6 | [N,36] DDSDDE.

__global__ __launch_bounds__(256) void nh3d_kernel(
    const float* __restrict__ F_in,
    const float* __restrict__ mat_par,
    float* __restrict__ out,
    int n, int vec_ok)
{
    int p = blockIdx.x * blockDim.x + threadIdx.x;
    if (p >= n) return;

    const float c1 = mat_par[0];
    const float c2 = mat_par[1];

    const float* Fp = F_in + (size_t)p * 9;
    float F[3][3];
    F[0][0] = __ldcs(Fp + 0); F[0][1] = __ldcs(Fp + 1); F[0][2] = __ldcs(Fp + 2);
    F[1][0] = __ldcs(Fp + 3); F[1][1] = __ldcs(Fp + 4); F[1][2] = __ldcs(Fp + 5);
    F[2][0] = __ldcs(Fp + 6); F[2][1] = __ldcs(Fp + 7); F[2][2] = __ldcs(Fp + 8);

    // B = F F^T (symmetric)
    float B[3][3];
    #pragma unroll
    for (int i = 0; i < 3; i++)
        #pragma unroll
        for (int j = 0; j < 3; j++)
            B[i][j] = F[i][0]*F[j][0] + F[i][1]*F[j][1] + F[i][2]*F[j][2];

    float J = F[0][0]*(F[1][1]*F[2][2] - F[1][2]*F[2][1])
            - F[0][1]*(F[1][0]*F[2][2] - F[1][2]*F[2][0])
            + F[0][2]*(F[1][0]*F[2][1] - F[1][1]*F[2][0]);

    float I1   = B[0][0] + B[1][1] + B[2][2];
    float Jm23 = 1.0f / cbrtf(J * J);      // J^{-2/3}
    float invJ = 1.0f / J;

    float a = 2.0f * c1 * Jm23;
    float b = 2.0f * c2 * (J - 1.0f) * J;

    // Kirchhoff stress tau = a*(B - I1/3 * I) + b*I
    float tau[3][3];
    #pragma unroll
    for (int i = 0; i < 3; i++)
        #pragma unroll
        for (int j = 0; j < 3; j++)
            tau[i][j] = a * (B[i][j] - (i == j ? I1 * (1.0f/3.0f) : 0.0f))
                      + (i == j ? b : 0.0f);

    float psi = c1 * (Jm23 * I1 - 3.0f) + c2 * (J - 1.0f) * (J - 1.0f);

    // Tangent coefficients (material part after push-forward):
    // Stiff_ijkl = c_dd d_ij d_kl + c_bd (B_ij d_kl + d_ij B_kl)
    //            + a d_ik B_jl + c_sw d_il d_jk
    //            + 0.5*(tau_ik d_jl + tau_il d_jk + tau_jk d_il - tau_jl d_ik)
    float c_dd = (2.0f/9.0f) * a * I1 + 2.0f * c2 * (2.0f*J - 1.0f) * J;
    float c_bd = -(2.0f/3.0f) * a;
    float c_sw = a * I1 * (1.0f/3.0f) - b;

    const int II[6] = {0, 1, 2, 0, 0, 1};
    const int JJ[6] = {0, 1, 2, 1, 2, 2};

    float cau[6];
    #pragma unroll
    for (int r = 0; r < 6; r++)
        cau[r] = tau[II[r]][JJ[r]] * invJ;

    float dd[36];
    #pragma unroll
    for (int r = 0; r < 6; r++) {
        const int i = II[r], j = JJ[r];
        #pragma unroll
        for (int c = 0; c < 6; c++) {
            const int k = II[c], l = JJ[c];
            float s = 0.0f;
            if (i == j && k == l) s += c_dd;
            if (k == l)           s += c_bd * B[i][j];
            if (i == j)           s += c_bd * B[k][l];
            if (i == k)           s += a * B[j][l];
            if (i == l && j == k) s += c_sw;
            // geometric correction
            float g = 0.0f;
            if (j == l) g += tau[i][k];
            if (j == k) g += tau[i][l];
            if (i == l) g += tau[j][k];
            if (i == k) g -= tau[j][l];
            s += 0.5f * g;
            dd[r*6 + c] = s * invJ;
        }
    }

    // ---- stores (streaming) ----
    __stcs(out + p, psi);

    float* cbase = out + (size_t)n + (size_t)p * 6;
    float* dbase = out + (size_t)n * 7 + (size_t)p * 36;

    if (vec_ok) {
        float2* c2p = reinterpret_cast<float2*>(cbase);
        __stcs(c2p + 0, make_float2(cau[0], cau[1]));
        __stcs(c2p + 1, make_float2(cau[2], cau[3]));
        __stcs(c2p + 2, make_float2(cau[4], cau[5]));
        float4* d4p = reinterpret_cast<float4*>(dbase);
        #pragma unroll
        for (int q = 0; q < 9; q++)
            __stcs(d4p + q, make_float4(dd[4*q+0], dd[4*q+1], dd[4*q+2], dd[4*q+3]));
    } else {
        #pragma unroll
        for (int q = 0; q < 6; q++) __stcs(cbase + q, cau[q]);
        #pragma unroll
        for (int q = 0; q < 36; q++) __stcs(dbase + q, dd[q]);
    }
}

extern "C" void kernel_launch(void* const* d_in, const int* in_sizes, int n_in,
                              void* d_out, int out_size) {
    const float* F_in    = (const float*)d_in[0];
    const float* mat_par = (const float*)d_in[1];
    float* out = (float*)d_out;
    int n = in_sizes[0] / 9;

    // vector path needs: (n*4) % 8 == 0 for float2 base and (7n*4) % 16 == 0 for float4 base
    int vec_ok = ((n % 4) == 0) ? 1 : 0;

    int threads = 256;
    int blocks = (n + threads - 1) / threads;
    nh3d_kernel<<<blocks, threads>>>(F_in, mat_par, out, n, vec_ok);
}

// round 2
// speedup vs baseline: 1.6226x; 1.6226x over previous
#include <cuda_runtime.h>

// Neo-Hookean 3D material point: psi, Cauchy (Voigt 6), DDSDDE (6x6) per point.
// Output layout (flattened tuple): [N] psi | [N,6] Cauchy6 | [N,36] DDSDDE.
//
// Strategy: smem-staged, fully-coalesced global loads/stores. Each thread owns
// one point; gmem traffic goes through shared memory so every LDG/STG is
// warp-coalesced (fixes the L1/L2 wavefront amplification seen in R0 ncu).

#define TPB 256
#define ROW 43   // 36 (dd) + 6 (cau) + 1 pad; 43 coprime with 32 -> conflict-free STS

__device__ __forceinline__ void nh3d_point(
    const float F[3][3], float c1, float c2,
    float& psi, float cau[6], float dd[36])
{
    // B = F F^T (symmetric)
    float B[3][3];
    #pragma unroll
    for (int i = 0; i < 3; i++)
        #pragma unroll
        for (int j = 0; j < 3; j++)
            B[i][j] = F[i][0]*F[j][0] + F[i][1]*F[j][1] + F[i][2]*F[j][2];

    float J = F[0][0]*(F[1][1]*F[2][2] - F[1][2]*F[2][1])
            - F[0][1]*(F[1][0]*F[2][2] - F[1][2]*F[2][0])
            + F[0][2]*(F[1][0]*F[2][1] - F[1][1]*F[2][0]);

    float I1   = B[0][0] + B[1][1] + B[2][2];
    float Jm23 = 1.0f / cbrtf(J * J);      // J^{-2/3}
    float invJ = 1.0f / J;

    float a = 2.0f * c1 * Jm23;
    float b = 2.0f * c2 * (J - 1.0f) * J;

    // Kirchhoff stress tau = a*(B - I1/3 * I) + b*I
    float tau[3][3];
    #pragma unroll
    for (int i = 0; i < 3; i++)
        #pragma unroll
        for (int j = 0; j < 3; j++)
            tau[i][j] = a * (B[i][j] - (i == j ? I1 * (1.0f/3.0f) : 0.0f))
                      + (i == j ? b : 0.0f);

    psi = c1 * (Jm23 * I1 - 3.0f) + c2 * (J - 1.0f) * (J - 1.0f);

    // Spatial tangent:
    // Stiff_ijkl = c_dd d_ij d_kl + c_bd (B_ij d_kl + d_ij B_kl)
    //            + a d_ik B_jl + c_sw d_il d_jk
    //            + 0.5*(tau_ik d_jl + tau_il d_jk + tau_jk d_il - tau_jl d_ik)
    float c_dd = (2.0f/9.0f) * a * I1 + 2.0f * c2 * (2.0f*J - 1.0f) * J;
    float c_bd = -(2.0f/3.0f) * a;
    float c_sw = a * I1 * (1.0f/3.0f) - b;

    const int II[6] = {0, 1, 2, 0, 0, 1};
    const int JJ[6] = {0, 1, 2, 1, 2, 2};

    #pragma unroll
    for (int r = 0; r < 6; r++)
        cau[r] = tau[II[r]][JJ[r]] * invJ;

    #pragma unroll
    for (int r = 0; r < 6; r++) {
        const int i = II[r], j = JJ[r];
        #pragma unroll
        for (int c = 0; c < 6; c++) {
            const int k = II[c], l = JJ[c];
            float s = 0.0f;
            if (i == j && k == l) s += c_dd;
            if (k == l)           s += c_bd * B[i][j];
            if (i == j)           s += c_bd * B[k][l];
            if (i == k)           s += a * B[j][l];
            if (i == l && j == k) s += c_sw;
            float g = 0.0f;
            if (j == l) g += tau[i][k];
            if (j == k) g += tau[i][l];
            if (i == l) g += tau[j][k];
            if (i == k) g -= tau[j][l];
            s += 0.5f * g;
            dd[r*6 + c] = s * invJ;
        }
    }
}

__global__ __launch_bounds__(TPB) void nh3d_kernel(
    const float* __restrict__ F_in,
    const float* __restrict__ mat_par,
    float* __restrict__ out,
    int n)
{
    __shared__ float sbuf[TPB * ROW];   // 44032 B

    const int tid = threadIdx.x;
    const int block_start = blockIdx.x * TPB;
    const float c1 = mat_par[0];
    const float c2 = mat_par[1];

    float F[3][3];
    float psi, cau[6], dd[36];

    if (block_start + TPB <= n) {
        // ---------------- full block: staged, coalesced path ----------------
        // Stage F: 256*9 floats = 576 float4, coalesced LDG.128
        {
            const float4* g4 = reinterpret_cast<const float4*>(F_in + (size_t)block_start * 9);
            float4* s4 = reinterpret_cast<float4*>(sbuf);
            #pragma unroll
            for (int v = tid; v < (TPB * 9) / 4; v += TPB)
                s4[v] = __ldcs(g4 + v);
        }
        __syncthreads();
        // read own F from smem: stride 9 (coprime 32) -> conflict-free
        #pragma unroll
        for (int i = 0; i < 9; i++)
            (&F[0][0])[i] = sbuf[tid * 9 + i];
        __syncthreads();   // everyone done reading before results overwrite sbuf

        nh3d_point(F, c1, c2, psi, cau, dd);

        // psi: already coalesced
        __stcs(out + block_start + tid, psi);

        // stage results: row pitch 43 -> conflict-free STS
        #pragma unroll
        for (int q = 0; q < 36; q++) sbuf[tid * ROW + q]      = dd[q];
        #pragma unroll
        for (int q = 0; q < 6;  q++) sbuf[tid * ROW + 36 + q] = cau[q];
        __syncthreads();

        // drain cau: 1536 floats, coalesced STG.32
        {
            float* cdst = out + (size_t)n + (size_t)block_start * 6;
            #pragma unroll
            for (int k = 0; k < 6; k++) {
                int t = tid + k * TPB;
                int p = t / 6, q = t - p * 6;
                __stcs(cdst + t, sbuf[p * ROW + 36 + q]);
            }
        }
        // drain dd: 9216 floats, coalesced STG.32
        {
            float* ddst = out + (size_t)n * 7 + (size_t)block_start * 36;
            #pragma unroll
            for (int k = 0; k < 36; k++) {
                int t = tid + k * TPB;
                int p = t / 36, q = t - p * 36;
                __stcs(ddst + t, sbuf[p * ROW + q]);
            }
        }
    } else {
        // ---------------- partial tail block: scalar fallback ----------------
        const int p = block_start + tid;
        if (p >= n) return;
        const float* Fp = F_in + (size_t)p * 9;
        #pragma unroll
        for (int i = 0; i < 9; i++)
            (&F[0][0])[i] = __ldcs(Fp + i);

        nh3d_point(F, c1, c2, psi, cau, dd);

        __stcs(out + p, psi);
        float* cbase = out + (size_t)n + (size_t)p * 6;
        #pragma unroll
        for (int q = 0; q < 6; q++) __stcs(cbase + q, cau[q]);
        float* dbase = out + (size_t)n * 7 + (size_t)p * 36;
        #pragma unroll
        for (int q = 0; q < 36; q++) __stcs(dbase + q, dd[q]);
    }
}

extern "C" void kernel_launch(void* const* d_in, const int* in_sizes, int n_in,
                              void* d_out, int out_size) {
    const float* F_in    = (const float*)d_in[0];
    const float* mat_par = (const float*)d_in[1];
    float* out = (float*)d_out;
    int n = in_sizes[0] / 9;

    int blocks = (n + TPB - 1) / TPB;
    nh3d_kernel<<<blocks, TPB>>>(F_in, mat_par, out, n);
}

// round 3
// speedup vs baseline: 1.6399x; 1.0107x over previous
#include <cuda_runtime.h>

// Neo-Hookean 3D material point: psi, Cauchy (Voigt 6), DDSDDE (6x6) per point.
// Output layout (flattened tuple): [N] psi | [N,6] Cauchy6 | [N,36] DDSDDE.
//
// R2: smem staging with pitch 44 (16B-aligned rows) so the entire result
// round-trip is 128-bit (STS.128 / LDS.128 / STG.128) — cuts L1 wavefront
// count ~2.7x vs R1's scalar staging (L1 was the binding pipe at 56%).

#define TPB 256
#define ROW 44   // 36 (dd) + 6 (cau) + 2 pad; divisible by 4 -> 16B-aligned rows

__device__ __forceinline__ void nh3d_point(
    const float F[3][3], float c1, float c2,
    float& psi, float cau[6], float dd[36])
{
    // B = F F^T (symmetric)
    float B[3][3];
    #pragma unroll
    for (int i = 0; i < 3; i++)
        #pragma unroll
        for (int j = 0; j < 3; j++)
            B[i][j] = F[i][0]*F[j][0] + F[i][1]*F[j][1] + F[i][2]*F[j][2];

    float J = F[0][0]*(F[1][1]*F[2][2] - F[1][2]*F[2][1])
            - F[0][1]*(F[1][0]*F[2][2] - F[1][2]*F[2][0])
            + F[0][2]*(F[1][0]*F[2][1] - F[1][1]*F[2][0]);

    float I1   = B[0][0] + B[1][1] + B[2][2];
    float Jm23 = 1.0f / cbrtf(J * J);      // J^{-2/3}
    float invJ = 1.0f / J;

    float a = 2.0f * c1 * Jm23;
    float b = 2.0f * c2 * (J - 1.0f) * J;

    // Kirchhoff stress tau = a*(B - I1/3 * I) + b*I
    float tau[3][3];
    #pragma unroll
    for (int i = 0; i < 3; i++)
        #pragma unroll
        for (int j = 0; j < 3; j++)
            tau[i][j] = a * (B[i][j] - (i == j ? I1 * (1.0f/3.0f) : 0.0f))
                      + (i == j ? b : 0.0f);

    psi = c1 * (Jm23 * I1 - 3.0f) + c2 * (J - 1.0f) * (J - 1.0f);

    // Spatial tangent:
    // Stiff_ijkl = c_dd d_ij d_kl + c_bd (B_ij d_kl + d_ij B_kl)
    //            + a d_ik B_jl + c_sw d_il d_jk
    //            + 0.5*(tau_ik d_jl + tau_il d_jk + tau_jk d_il - tau_jl d_ik)
    float c_dd = (2.0f/9.0f) * a * I1 + 2.0f * c2 * (2.0f*J - 1.0f) * J;
    float c_bd = -(2.0f/3.0f) * a;
    float c_sw = a * I1 * (1.0f/3.0f) - b;

    const int II[6] = {0, 1, 2, 0, 0, 1};
    const int JJ[6] = {0, 1, 2, 1, 2, 2};

    #pragma unroll
    for (int r = 0; r < 6; r++)
        cau[r] = tau[II[r]][JJ[r]] * invJ;

    #pragma unroll
    for (int r = 0; r < 6; r++) {
        const int i = II[r], j = JJ[r];
        #pragma unroll
        for (int c = 0; c < 6; c++) {
            const int k = II[c], l = JJ[c];
            float s = 0.0f;
            if (i == j && k == l) s += c_dd;
            if (k == l)           s += c_bd * B[i][j];
            if (i == j)           s += c_bd * B[k][l];
            if (i == k)           s += a * B[j][l];
            if (i == l && j == k) s += c_sw;
            float g = 0.0f;
            if (j == l) g += tau[i][k];
            if (j == k) g += tau[i][l];
            if (i == l) g += tau[j][k];
            if (i == k) g -= tau[j][l];
            s += 0.5f * g;
            dd[r*6 + c] = s * invJ;
        }
    }
}

__global__ __launch_bounds__(TPB) void nh3d_kernel(
    const float* __restrict__ F_in,
    const float* __restrict__ mat_par,
    float* __restrict__ out,
    int n, int vec_ok)
{
    __shared__ float sbuf[TPB * ROW];   // 45056 B

    const int tid = threadIdx.x;
    const int block_start = blockIdx.x * TPB;
    const float c1 = mat_par[0];
    const float c2 = mat_par[1];

    float F[3][3];
    float psi, cau[6], dd[36];

    if (vec_ok && block_start + TPB <= n) {
        // ---------------- full block: staged, vectorized path ----------------
        // Stage F: 256*9 floats = 576 float4, coalesced LDG.128 -> STS.128
        {
            const float4* g4 = reinterpret_cast<const float4*>(F_in + (size_t)block_start * 9);
            float4* s4 = reinterpret_cast<float4*>(sbuf);
            #pragma unroll
            for (int v = tid; v < (TPB * 9) / 4; v += TPB)
                s4[v] = __ldcs(g4 + v);
        }
        __syncthreads();
        #pragma unroll
        for (int i = 0; i < 9; i++)
            (&F[0][0])[i] = sbuf[tid * 9 + i];
        __syncthreads();   // done reading before results overwrite sbuf

        nh3d_point(F, c1, c2, psi, cau, dd);

        // psi: already coalesced
        __stcs(out + block_start + tid, psi);

        // stage results vectorized: row base 16B-aligned (ROW=44)
        {
            float4* row4 = reinterpret_cast<float4*>(sbuf + tid * ROW);
            #pragma unroll
            for (int q = 0; q < 9; q++)
                row4[q] = make_float4(dd[4*q+0], dd[4*q+1], dd[4*q+2], dd[4*q+3]);
            float2* row2 = reinterpret_cast<float2*>(sbuf + tid * ROW + 36);
            #pragma unroll
            for (int q = 0; q < 3; q++)
                row2[q] = make_float2(cau[2*q+0], cau[2*q+1]);
        }
        __syncthreads();

        // drain cau: 768 float2 per block, LDS.64 -> STG.64
        {
            float2* cdst = reinterpret_cast<float2*>(out + (size_t)n + (size_t)block_start * 6);
            #pragma unroll
            for (int k = 0; k < 3; k++) {
                int t2 = tid + k * TPB;
                int p = t2 / 3, q2 = t2 - p * 3;
                float2 v = *reinterpret_cast<const float2*>(sbuf + p * ROW + 36 + q2 * 2);
                __stcs(cdst + t2, v);
            }
        }
        // drain dd: 2304 float4 per block, LDS.128 -> STG.128
        {
            float4* ddst = reinterpret_cast<float4*>(out + (size_t)n * 7 + (size_t)block_start * 36);
            #pragma unroll
            for (int k = 0; k < 9; k++) {
                int t4 = tid + k * TPB;
                int p = t4 / 9, q4 = t4 - p * 9;
                float4 v = *reinterpret_cast<const float4*>(sbuf + p * ROW + q4 * 4);
                __stcs(ddst + t4, v);
            }
        }
    } else {
        // ---------------- tail / unaligned fallback: scalar path ----------------
        const int p = block_start + tid;
        if (p >= n) return;
        const float* Fp = F_in + (size_t)p * 9;
        #pragma unroll
        for (int i = 0; i < 9; i++)
            (&F[0][0])[i] = __ldcs(Fp + i);

        nh3d_point(F, c1, c2, psi, cau, dd);

        __stcs(out + p, psi);
        float* cbase = out + (size_t)n + (size_t)p * 6;
        #pragma unroll
        for (int q = 0; q < 6; q++) __stcs(cbase + q, cau[q]);
        float* dbase = out + (size_t)n * 7 + (size_t)p * 36;
        #pragma unroll
        for (int q = 0; q < 36; q++) __stcs(dbase + q, dd[q]);
    }
}

extern "C" void kernel_launch(void* const* d_in, const int* in_sizes, int n_in,
                              void* d_out, int out_size) {
    const float* F_in    = (const float*)d_in[0];
    const float* mat_par = (const float*)d_in[1];
    float* out = (float*)d_out;
    int n = in_sizes[0] / 9;

    // vector path alignment: dd base (7n floats) needs 16B (n%4==0),
    // cau base (n floats) needs 8B (n%2==0).
    int vec_ok = ((n % 4) == 0) ? 1 : 0;

    int blocks = (n + TPB - 1) / TPB;
    nh3d_kernel<<<blocks, TPB>>>(F_in, mat_par, out, n, vec_ok);
}